// round 16
// baseline (speedup 1.0000x reference)
#include <cuda_runtime.h>
#include <cuda_fp16.h>

#define N_NODES 100000
#define N_EDGES 1600000
#define IN_F 128
#define HID_F 64
#define CLS_F 32
#define NBLK 391                      // ceil(N_NODES/256)
#define COL_CAP (N_EDGES + 4 * N_NODES)

// ---------------- scratch (16B-aligned; +1 sentinel row, always zero) -------
__device__ __align__(16) float gv56_xw1[N_NODES * HID_F];          // x @ W1 (fp32)
__device__ __align__(16) __half2 gv56_xwsh[(N_NODES + 1) * 32];    // dinv*xw1 fp16; row N = 0
__device__ __align__(16) float gv56_h1 [N_NODES * HID_F];
__device__ __align__(16) float gv56_hw2s[(N_NODES + 1) * CLS_F];   // dinv*(h@W2); row N = 0
__device__ __align__(16) float gv56_dinv[N_NODES];
__device__ int   gv56_cnt[N_NODES];   // zero at entry; re-zeroed by k_scan
__device__ int   gv56_rowptr[N_NODES + 1];
__device__ int   gv56_cursor[N_NODES];
__device__ __align__(16) int gv56_col[COL_CAP];
__device__ unsigned long long gv56_lb[512];   // lookback; zeroed by k_count

// ---------------- per-block edge dtype probe ---------------------------------
__device__ __forceinline__ bool detect_is64(const void* __restrict__ ei) {
    const long long* p = (const long long*)ei;
    bool ok = true;
#pragma unroll
    for (int i = 0; i < 4; i++) {
        long long v = p[i];
        ok &= (v >= 0) && (v < (long long)N_NODES);
    }
    return ok;
}

// ---------------- count: degrees + zero lookback flags ------------------------
__global__ __launch_bounds__(256) void k_count(const void* __restrict__ ei) {
    __shared__ int s64;
    if (threadIdx.x == 0) s64 = detect_is64(ei) ? 1 : 0;
    if (blockIdx.x < 2) {
        int idx = blockIdx.x * 256 + threadIdx.x;
        gv56_lb[idx] = 0ull;
    }
    __syncthreads();
    const bool is64 = (s64 != 0);
    int e0 = (blockIdx.x * 256 + threadIdx.x) * 4;
    if (e0 >= N_EDGES) return;
    int d[4];
    if (is64) {
        const long long* p = (const long long*)ei;
#pragma unroll
        for (int i = 0; i < 4; i++)
            d[i] = (e0 + i < N_EDGES) ? (int)p[(long long)N_EDGES + e0 + i] : -1;
    } else {
        int4 dd = *(const int4*)&((const int*)ei)[N_EDGES + e0];
        d[0] = dd.x; d[1] = dd.y; d[2] = dd.z; d[3] = dd.w;
#pragma unroll
        for (int i = 0; i < 4; i++)
            if (e0 + i >= N_EDGES) d[i] = -1;
    }
#pragma unroll
    for (int i = 0; i < 4; i++)
        if ((unsigned)d[i] < (unsigned)N_NODES) atomicAdd(&gv56_cnt[d[i]], 1);
}

// ---------------- single-pass lookback scan -----------------------------------
__global__ __launch_bounds__(256) void k_scan(int dummy) {
    __shared__ int s[256];
    __shared__ int red[8];
    const int t = threadIdx.x;
    const int b = blockIdx.x;

    int i = b * 256 + t;
    int v = 0, pv = 0;
    if (i < N_NODES) {
        v = gv56_cnt[i];
        pv = (v + 3) & ~3;
    }

    int agg = pv;
#pragma unroll
    for (int o = 16; o; o >>= 1) agg += __shfl_down_sync(0xffffffffu, agg, o);
    if ((t & 31) == 0) red[t >> 5] = agg;
    __syncthreads();
    if (t < 8) {
        int sr = red[t];
#pragma unroll
        for (int o = 4; o; o >>= 1) sr += __shfl_down_sync(0xffu, sr, o);
        if (t == 0) {
            red[0] = sr;
            gv56_lb[b] = (1ull << 32) | (unsigned long long)(unsigned)sr;
        }
    }
    __syncthreads();

    int part = 0;
    for (int j = t; j < b; j += 256) {
        unsigned long long w;
        do {
            w = *((volatile unsigned long long*)&gv56_lb[j]);
        } while ((w >> 32) == 0ull);
        part += (int)(unsigned)w;
    }
#pragma unroll
    for (int o = 16; o; o >>= 1) part += __shfl_down_sync(0xffffffffu, part, o);
    if ((t & 31) == 0) red[t >> 5] = part;
    __syncthreads();
    if (t < 8) {
        int sr = red[t];
#pragma unroll
        for (int o = 4; o; o >>= 1) sr += __shfl_down_sync(0xffu, sr, o);
        if (t == 0) red[0] = sr;
    }
    __syncthreads();
    const int off = red[0];

    s[t] = pv;
    __syncthreads();
    for (int o = 1; o < 256; o <<= 1) {
        int a = 0;
        if (t >= o) a = s[t - o];
        __syncthreads();
        s[t] += a;
        __syncthreads();
    }
    if (i < N_NODES) {
        int r = off + s[t] - pv;
        gv56_rowptr[i] = r;
        gv56_cursor[i] = r;
        gv56_dinv[i] = rsqrtf((float)(v + 1));
        gv56_cnt[i] = 0;
        for (int q = r + v; q < r + pv; q++) gv56_col[q] = N_NODES;
        if (i == N_NODES - 1) gv56_rowptr[N_NODES] = r + pv;
    }
}

// ---------------- fill: 4 edges per thread ------------------------------------
__global__ __launch_bounds__(256) void k_fill(const void* __restrict__ ei) {
    __shared__ int s64;
    if (threadIdx.x == 0) s64 = detect_is64(ei) ? 1 : 0;
    __syncthreads();
    const bool is64 = (s64 != 0);
    int e0 = (blockIdx.x * 256 + threadIdx.x) * 4;
    if (e0 >= N_EDGES) return;
    int sarr[4], darr[4];
    if (is64) {
        const long long* p = (const long long*)ei;
#pragma unroll
        for (int i = 0; i < 4; i++) {
            if (e0 + i < N_EDGES) {
                sarr[i] = (int)p[e0 + i];
                darr[i] = (int)p[(long long)N_EDGES + e0 + i];
            } else { sarr[i] = -1; darr[i] = -1; }
        }
    } else {
        int4 ss = *(const int4*)&((const int*)ei)[e0];
        int4 dd = *(const int4*)&((const int*)ei)[N_EDGES + e0];
        sarr[0] = ss.x; sarr[1] = ss.y; sarr[2] = ss.z; sarr[3] = ss.w;
        darr[0] = dd.x; darr[1] = dd.y; darr[2] = dd.z; darr[3] = dd.w;
#pragma unroll
        for (int i = 0; i < 4; i++)
            if (e0 + i >= N_EDGES) { sarr[i] = -1; darr[i] = -1; }
    }
#pragma unroll
    for (int i = 0; i < 4; i++) {
        if ((unsigned)darr[i] < (unsigned)N_NODES &&
            (unsigned)sarr[i] < (unsigned)N_NODES) {
            int slot = atomicAdd(&gv56_cursor[darr[i]], 1);
            gv56_col[slot] = sarr[i];
        }
    }
}

// ---------------- GEMM1 (R6 winner): xw1 = X @ W1 ----------------------------
__global__ __launch_bounds__(256) void k_gemm1(const float* __restrict__ X,
                                               const float* __restrict__ W) {
    __shared__ __align__(16) float sW[IN_F * HID_F];   // 32 KB
    __shared__ __align__(16) float sX[64 * 36];        // 9 KB

    const int tid = threadIdx.x;
    const int m0 = blockIdx.x * 64;
    const int ty = tid >> 4;
    const int tx = tid & 15;

    for (int i = tid; i < IN_F * HID_F / 4; i += 256)
        ((float4*)sW)[i] = ((const float4*)W)[i];

    float acc[4][4];
#pragma unroll
    for (int i = 0; i < 4; i++)
#pragma unroll
        for (int j = 0; j < 4; j++) acc[i][j] = 0.0f;

    for (int kt = 0; kt < IN_F; kt += 32) {
        __syncthreads();
        for (int i = tid; i < 64 * 8; i += 256) {
            int r = i >> 3, c4 = i & 7;
            int gr = m0 + r;
            float4 v = make_float4(0.f, 0.f, 0.f, 0.f);
            if (gr < N_NODES)
                v = *(const float4*)&X[(size_t)gr * IN_F + kt + c4 * 4];
            *(float4*)&sX[r * 36 + c4 * 4] = v;
        }
        __syncthreads();

#pragma unroll
        for (int kk = 0; kk < 32; kk++) {
            float4 w4 = ((const float4*)(sW + (kt + kk) * HID_F))[tx];
            float a0 = sX[(ty * 4 + 0) * 36 + kk];
            float a1 = sX[(ty * 4 + 1) * 36 + kk];
            float a2 = sX[(ty * 4 + 2) * 36 + kk];
            float a3 = sX[(ty * 4 + 3) * 36 + kk];
            acc[0][0] = fmaf(a0, w4.x, acc[0][0]);
            acc[0][1] = fmaf(a0, w4.y, acc[0][1]);
            acc[0][2] = fmaf(a0, w4.z, acc[0][2]);
            acc[0][3] = fmaf(a0, w4.w, acc[0][3]);
            acc[1][0] = fmaf(a1, w4.x, acc[1][0]);
            acc[1][1] = fmaf(a1, w4.y, acc[1][1]);
            acc[1][2] = fmaf(a1, w4.z, acc[1][2]);
            acc[1][3] = fmaf(a1, w4.w, acc[1][3]);
            acc[2][0] = fmaf(a2, w4.x, acc[2][0]);
            acc[2][1] = fmaf(a2, w4.y, acc[2][1]);
            acc[2][2] = fmaf(a2, w4.z, acc[2][2]);
            acc[2][3] = fmaf(a2, w4.w, acc[2][3]);
            acc[3][0] = fmaf(a3, w4.x, acc[3][0]);
            acc[3][1] = fmaf(a3, w4.y, acc[3][1]);
            acc[3][2] = fmaf(a3, w4.z, acc[3][2]);
            acc[3][3] = fmaf(a3, w4.w, acc[3][3]);
        }
    }

#pragma unroll
    for (int i = 0; i < 4; i++) {
        int gr = m0 + ty * 4 + i;
        if (gr < N_NODES) {
            float4 o = make_float4(acc[i][0], acc[i][1], acc[i][2], acc[i][3]);
            *(float4*)&gv56_xw1[(size_t)gr * HID_F + tx * 4] = o;
        }
    }
}

// ---------------- scale+compress: xwsh = half(dinv ⊙ xw1) --------------------
__global__ __launch_bounds__(256) void k_scale() {
    int i = blockIdx.x * 256 + threadIdx.x;   // float4 group index; grid 6250
    int row = i >> 4;
    float dv = gv56_dinv[row];
    float4 v = ((const float4*)gv56_xw1)[i];
    __half2 h0 = __floats2half2_rn(v.x * dv, v.y * dv);
    __half2 h1 = __floats2half2_rn(v.z * dv, v.w * dv);
    uint2 packed;
    packed.x = *(const unsigned*)&h0;
    packed.y = *(const unsigned*)&h1;
    *(uint2*)&gv56_xwsh[i * 2] = packed;      // 8 bytes at half2 index i*2
}

// ---------------- prop1: h = relu(dv*(dv*xw1[v] + sum xwsh[u]) + b1) ---------
// warp per node; neighbor rows fp16 (128B), self term fp32.
__global__ __launch_bounds__(256) void k_prop1(const float* __restrict__ b1) {
    const int warp = threadIdx.x >> 5;
    const int lane = threadIdx.x & 31;
    const int v = blockIdx.x * 8 + warp;      // grid 12500 exact

    const __half2* __restrict__ xwh = gv56_xwsh;
    float dv = gv56_dinv[v];
    float2 self = ((const float2*)gv56_xw1)[(size_t)v * 32 + lane];
    float ax = dv * self.x;                    // == xws[v] in fp32
    float ay = dv * self.y;

    int p = gv56_rowptr[v];
    const int e = gv56_rowptr[v + 1];         // (e - p) % 4 == 0
    for (; p + 8 <= e; p += 8) {
        int4 c0 = *(const int4*)&gv56_col[p];
        int4 c1 = *(const int4*)&gv56_col[p + 4];
        float2 f0 = __half22float2(xwh[(size_t)c0.x * 32 + lane]);
        float2 f1 = __half22float2(xwh[(size_t)c0.y * 32 + lane]);
        float2 f2 = __half22float2(xwh[(size_t)c0.z * 32 + lane]);
        float2 f3 = __half22float2(xwh[(size_t)c0.w * 32 + lane]);
        float2 f4 = __half22float2(xwh[(size_t)c1.x * 32 + lane]);
        float2 f5 = __half22float2(xwh[(size_t)c1.y * 32 + lane]);
        float2 f6 = __half22float2(xwh[(size_t)c1.z * 32 + lane]);
        float2 f7 = __half22float2(xwh[(size_t)c1.w * 32 + lane]);
        ax += f0.x + f1.x + f2.x + f3.x + f4.x + f5.x + f6.x + f7.x;
        ay += f0.y + f1.y + f2.y + f3.y + f4.y + f5.y + f6.y + f7.y;
    }
    if (p < e) {
        int4 c0 = *(const int4*)&gv56_col[p];
        float2 f0 = __half22float2(xwh[(size_t)c0.x * 32 + lane]);
        float2 f1 = __half22float2(xwh[(size_t)c0.y * 32 + lane]);
        float2 f2 = __half22float2(xwh[(size_t)c0.z * 32 + lane]);
        float2 f3 = __half22float2(xwh[(size_t)c0.w * 32 + lane]);
        ax += f0.x + f1.x + f2.x + f3.x;
        ay += f0.y + f1.y + f2.y + f3.y;
    }

    float2 bb = ((const float2*)b1)[lane];
    float hx = fmaxf(fmaf(ax, dv, bb.x), 0.0f);
    float hy = fmaxf(fmaf(ay, dv, bb.y), 0.0f);
    ((float2*)gv56_h1)[(size_t)v * 32 + lane] = make_float2(hx, hy);
}

// ---------------- GEMM2: hw2s = dinv ⊙ (h1 @ W2) -----------------------------
__global__ __launch_bounds__(256) void k_gemm2(const float* __restrict__ W2) {
    __shared__ __align__(16) float sW[HID_F * CLS_F];  // 8 KB
    __shared__ __align__(16) float sX[64 * 68];        // 17.4 KB

    const int tid = threadIdx.x;
    const int m0 = blockIdx.x * 64;
    const int tx = tid & 7;
    const int ty = tid >> 3;

    for (int i = tid; i < HID_F * CLS_F / 4; i += 256)
        ((float4*)sW)[i] = ((const float4*)W2)[i];

    for (int i = tid; i < 64 * 16; i += 256) {
        int r = i >> 4, c4 = i & 15;
        int gr = m0 + r;
        float4 vv = make_float4(0.f, 0.f, 0.f, 0.f);
        if (gr < N_NODES)
            vv = *(const float4*)&gv56_h1[(size_t)gr * HID_F + c4 * 4];
        *(float4*)&sX[r * 68 + c4 * 4] = vv;
    }
    __syncthreads();

    float acc[2][4] = {{0.f, 0.f, 0.f, 0.f}, {0.f, 0.f, 0.f, 0.f}};
#pragma unroll
    for (int k = 0; k < HID_F; k++) {
        float4 w4 = *(const float4*)&sW[k * CLS_F + tx * 4];
        float a0 = sX[(ty * 2 + 0) * 68 + k];
        float a1 = sX[(ty * 2 + 1) * 68 + k];
        acc[0][0] = fmaf(a0, w4.x, acc[0][0]);
        acc[0][1] = fmaf(a0, w4.y, acc[0][1]);
        acc[0][2] = fmaf(a0, w4.z, acc[0][2]);
        acc[0][3] = fmaf(a0, w4.w, acc[0][3]);
        acc[1][0] = fmaf(a1, w4.x, acc[1][0]);
        acc[1][1] = fmaf(a1, w4.y, acc[1][1]);
        acc[1][2] = fmaf(a1, w4.z, acc[1][2]);
        acc[1][3] = fmaf(a1, w4.w, acc[1][3]);
    }

#pragma unroll
    for (int i = 0; i < 2; i++) {
        int gr = m0 + ty * 2 + i;
        if (gr < N_NODES) {
            float dv = gv56_dinv[gr];
            float4 o = make_float4(acc[i][0] * dv, acc[i][1] * dv,
                                   acc[i][2] * dv, acc[i][3] * dv);
            *(float4*)&gv56_hw2s[(size_t)gr * CLS_F + tx * 4] = o;
        }
    }
}

// ---------------- prop2: out[v] = dv*(hw2s[v] + sum hw2s[u]) + b2 ------------
__global__ __launch_bounds__(256) void k_prop2(const float* __restrict__ b2,
                                               float* __restrict__ out) {
    const int warp = threadIdx.x >> 5;
    const int lane = threadIdx.x & 31;
    const int v = blockIdx.x * 8 + warp;      // grid 12500 exact

    float dv = gv56_dinv[v];
    float acc = gv56_hw2s[(size_t)v * CLS_F + lane];

    int p = gv56_rowptr[v];
    const int e = gv56_rowptr[v + 1];
    for (; p + 8 <= e; p += 8) {
        int4 c0 = *(const int4*)&gv56_col[p];
        int4 c1 = *(const int4*)&gv56_col[p + 4];
        float f0 = gv56_hw2s[(size_t)c0.x * CLS_F + lane];
        float f1 = gv56_hw2s[(size_t)c0.y * CLS_F + lane];
        float f2 = gv56_hw2s[(size_t)c0.z * CLS_F + lane];
        float f3 = gv56_hw2s[(size_t)c0.w * CLS_F + lane];
        float f4 = gv56_hw2s[(size_t)c1.x * CLS_F + lane];
        float f5 = gv56_hw2s[(size_t)c1.y * CLS_F + lane];
        float f6 = gv56_hw2s[(size_t)c1.z * CLS_F + lane];
        float f7 = gv56_hw2s[(size_t)c1.w * CLS_F + lane];
        acc += f0 + f1 + f2 + f3 + f4 + f5 + f6 + f7;
    }
    if (p < e) {
        int4 c0 = *(const int4*)&gv56_col[p];
        acc += gv56_hw2s[(size_t)c0.x * CLS_F + lane]
             + gv56_hw2s[(size_t)c0.y * CLS_F + lane]
             + gv56_hw2s[(size_t)c0.z * CLS_F + lane]
             + gv56_hw2s[(size_t)c0.w * CLS_F + lane];
    }
    out[(size_t)v * CLS_F + lane] = fmaf(acc, dv, b2[lane]);
}

// ---------------- launch ------------------------------------------------------
extern "C" void kernel_launch(void* const* d_in, const int* in_sizes, int n_in,
                              void* d_out, int out_size) {
    static cudaStream_t s2 = nullptr;
    static cudaEvent_t evFork = nullptr, evScan = nullptr, evScale = nullptr;
    if (s2 == nullptr) {
        int loPri = 0, hiPri = 0;
        cudaDeviceGetStreamPriorityRange(&loPri, &hiPri);
        cudaStreamCreateWithPriority(&s2, cudaStreamNonBlocking, hiPri);
        cudaEventCreateWithFlags(&evFork, cudaEventDisableTiming);
        cudaEventCreateWithFlags(&evScan, cudaEventDisableTiming);
        cudaEventCreateWithFlags(&evScale, cudaEventDisableTiming);
    }

    const float* x  = nullptr;
    const void*  ei = nullptr;
    const float* W1 = nullptr;
    const float* b1 = nullptr;
    const float* W2 = nullptr;
    const float* b2 = nullptr;

    for (int i = 0; i < n_in; i++) {
        switch (in_sizes[i]) {
            case N_NODES * IN_F:  x  = (const float*)d_in[i]; break;
            case 2 * N_EDGES:     ei = d_in[i];               break;
            case N_EDGES:         /* edge_attr unused */       break;
            case IN_F * HID_F:    W1 = (const float*)d_in[i]; break;
            case HID_F:           b1 = (const float*)d_in[i]; break;
            case HID_F * CLS_F:   W2 = (const float*)d_in[i]; break;
            case CLS_F:           b2 = (const float*)d_in[i]; break;
            default: break;
        }
    }
    if (!x)  x  = (const float*)d_in[0];
    if (!ei) ei = d_in[1];
    if (!W1 && n_in > 3) W1 = (const float*)d_in[3];
    if (!b1 && n_in > 4) b1 = (const float*)d_in[4];
    if (!W2 && n_in > 5) W2 = (const float*)d_in[5];
    if (!b2 && n_in > 6) b2 = (const float*)d_in[6];

    float* out = (float*)d_out;

    // fork: gemm1 (high-priority s2) ∥ CSR build (main)
    cudaEventRecord(evFork, 0);
    cudaStreamWaitEvent(s2, evFork, 0);
    k_gemm1<<<(N_NODES + 63) / 64, 256, 0, s2>>>(x, W1);

    k_count<<<(N_EDGES / 4 + 255) / 256, 256>>>(ei);
    k_scan <<<NBLK, 256>>>(0);
    cudaEventRecord(evScan, 0);
    cudaStreamWaitEvent(s2, evScan, 0);
    k_scale<<<N_NODES * HID_F / 4 / 256, 256, 0, s2>>>();
    cudaEventRecord(evScale, s2);

    k_fill <<<(N_EDGES / 4 + 255) / 256, 256>>>(ei);

    cudaStreamWaitEvent(0, evScale, 0);
    k_prop1<<<N_NODES / 8, 256>>>(b1);
    k_gemm2<<<(N_NODES + 63) / 64, 256>>>(W2);
    k_prop2<<<N_NODES / 8, 256>>>(b2, out);
}

// round 17
// speedup vs baseline: 1.0115x; 1.0115x over previous
#include <cuda_runtime.h>
#include <cuda_fp16.h>

#define N_NODES 100000
#define N_EDGES 1600000
#define IN_F 128
#define HID_F 64
#define CLS_F 32
#define NBLK 391                      // ceil(N_NODES/256)
#define COL_CAP (N_EDGES + 4 * N_NODES)

// ---------------- scratch (16B-aligned; +1 sentinel row, always zero) -------
__device__ __align__(16) float gv56_xw1[N_NODES * HID_F];          // x @ W1 (fp32)
__device__ __align__(16) __half2 gv56_xwsh[(N_NODES + 1) * 32];    // dinv*xw1 fp16; row N = 0
__device__ __align__(16) float gv56_h1 [N_NODES * HID_F];
__device__ __align__(16) float gv56_hw2s[(N_NODES + 1) * CLS_F];   // dinv*(h@W2); row N = 0
__device__ __align__(16) float gv56_dinv[N_NODES];
__device__ int   gv56_cnt[N_NODES];   // zero at entry; re-zeroed by k_scan
__device__ int   gv56_rowptr[N_NODES + 1];
__device__ int   gv56_cursor[N_NODES];
__device__ __align__(16) int gv56_col[COL_CAP];
__device__ unsigned long long gv56_lb[512];   // lookback; zeroed by k_count

// ---------------- per-block edge dtype probe ---------------------------------
__device__ __forceinline__ bool detect_is64(const void* __restrict__ ei) {
    const long long* p = (const long long*)ei;
    bool ok = true;
#pragma unroll
    for (int i = 0; i < 4; i++) {
        long long v = p[i];
        ok &= (v >= 0) && (v < (long long)N_NODES);
    }
    return ok;
}

// ---------------- count: degrees + zero lookback flags ------------------------
__global__ __launch_bounds__(256) void k_count(const void* __restrict__ ei) {
    __shared__ int s64;
    if (threadIdx.x == 0) s64 = detect_is64(ei) ? 1 : 0;
    if (blockIdx.x < 2) {
        int idx = blockIdx.x * 256 + threadIdx.x;
        gv56_lb[idx] = 0ull;
    }
    __syncthreads();
    const bool is64 = (s64 != 0);
    int e0 = (blockIdx.x * 256 + threadIdx.x) * 4;
    if (e0 >= N_EDGES) return;
    int d[4];
    if (is64) {
        const long long* p = (const long long*)ei;
#pragma unroll
        for (int i = 0; i < 4; i++)
            d[i] = (e0 + i < N_EDGES) ? (int)p[(long long)N_EDGES + e0 + i] : -1;
    } else {
        int4 dd = *(const int4*)&((const int*)ei)[N_EDGES + e0];
        d[0] = dd.x; d[1] = dd.y; d[2] = dd.z; d[3] = dd.w;
#pragma unroll
        for (int i = 0; i < 4; i++)
            if (e0 + i >= N_EDGES) d[i] = -1;
    }
#pragma unroll
    for (int i = 0; i < 4; i++)
        if ((unsigned)d[i] < (unsigned)N_NODES) atomicAdd(&gv56_cnt[d[i]], 1);
}

// ---------------- single-pass lookback scan -----------------------------------
__global__ __launch_bounds__(256) void k_scan(int dummy) {
    __shared__ int s[256];
    __shared__ int red[8];
    const int t = threadIdx.x;
    const int b = blockIdx.x;

    int i = b * 256 + t;
    int v = 0, pv = 0;
    if (i < N_NODES) {
        v = gv56_cnt[i];
        pv = (v + 3) & ~3;
    }

    int agg = pv;
#pragma unroll
    for (int o = 16; o; o >>= 1) agg += __shfl_down_sync(0xffffffffu, agg, o);
    if ((t & 31) == 0) red[t >> 5] = agg;
    __syncthreads();
    if (t < 8) {
        int sr = red[t];
#pragma unroll
        for (int o = 4; o; o >>= 1) sr += __shfl_down_sync(0xffu, sr, o);
        if (t == 0) {
            red[0] = sr;
            gv56_lb[b] = (1ull << 32) | (unsigned long long)(unsigned)sr;
        }
    }
    __syncthreads();

    int part = 0;
    for (int j = t; j < b; j += 256) {
        unsigned long long w;
        do {
            w = *((volatile unsigned long long*)&gv56_lb[j]);
        } while ((w >> 32) == 0ull);
        part += (int)(unsigned)w;
    }
#pragma unroll
    for (int o = 16; o; o >>= 1) part += __shfl_down_sync(0xffffffffu, part, o);
    if ((t & 31) == 0) red[t >> 5] = part;
    __syncthreads();
    if (t < 8) {
        int sr = red[t];
#pragma unroll
        for (int o = 4; o; o >>= 1) sr += __shfl_down_sync(0xffu, sr, o);
        if (t == 0) red[0] = sr;
    }
    __syncthreads();
    const int off = red[0];

    s[t] = pv;
    __syncthreads();
    for (int o = 1; o < 256; o <<= 1) {
        int a = 0;
        if (t >= o) a = s[t - o];
        __syncthreads();
        s[t] += a;
        __syncthreads();
    }
    if (i < N_NODES) {
        int r = off + s[t] - pv;
        gv56_rowptr[i] = r;
        gv56_cursor[i] = r;
        gv56_dinv[i] = rsqrtf((float)(v + 1));
        gv56_cnt[i] = 0;
        for (int q = r + v; q < r + pv; q++) gv56_col[q] = N_NODES;
        if (i == N_NODES - 1) gv56_rowptr[N_NODES] = r + pv;
    }
}

// ---------------- fill: 4 edges per thread ------------------------------------
__global__ __launch_bounds__(256) void k_fill(const void* __restrict__ ei) {
    __shared__ int s64;
    if (threadIdx.x == 0) s64 = detect_is64(ei) ? 1 : 0;
    __syncthreads();
    const bool is64 = (s64 != 0);
    int e0 = (blockIdx.x * 256 + threadIdx.x) * 4;
    if (e0 >= N_EDGES) return;
    int sarr[4], darr[4];
    if (is64) {
        const long long* p = (const long long*)ei;
#pragma unroll
        for (int i = 0; i < 4; i++) {
            if (e0 + i < N_EDGES) {
                sarr[i] = (int)p[e0 + i];
                darr[i] = (int)p[(long long)N_EDGES + e0 + i];
            } else { sarr[i] = -1; darr[i] = -1; }
        }
    } else {
        int4 ss = *(const int4*)&((const int*)ei)[e0];
        int4 dd = *(const int4*)&((const int*)ei)[N_EDGES + e0];
        sarr[0] = ss.x; sarr[1] = ss.y; sarr[2] = ss.z; sarr[3] = ss.w;
        darr[0] = dd.x; darr[1] = dd.y; darr[2] = dd.z; darr[3] = dd.w;
#pragma unroll
        for (int i = 0; i < 4; i++)
            if (e0 + i >= N_EDGES) { sarr[i] = -1; darr[i] = -1; }
    }
#pragma unroll
    for (int i = 0; i < 4; i++) {
        if ((unsigned)darr[i] < (unsigned)N_NODES &&
            (unsigned)sarr[i] < (unsigned)N_NODES) {
            int slot = atomicAdd(&gv56_cursor[darr[i]], 1);
            gv56_col[slot] = sarr[i];
        }
    }
}

// ---------------- GEMM1 (R6 winner): xw1 = X @ W1 ----------------------------
__global__ __launch_bounds__(256) void k_gemm1(const float* __restrict__ X,
                                               const float* __restrict__ W) {
    __shared__ __align__(16) float sW[IN_F * HID_F];   // 32 KB
    __shared__ __align__(16) float sX[64 * 36];        // 9 KB

    const int tid = threadIdx.x;
    const int m0 = blockIdx.x * 64;
    const int ty = tid >> 4;
    const int tx = tid & 15;

    for (int i = tid; i < IN_F * HID_F / 4; i += 256)
        ((float4*)sW)[i] = ((const float4*)W)[i];

    float acc[4][4];
#pragma unroll
    for (int i = 0; i < 4; i++)
#pragma unroll
        for (int j = 0; j < 4; j++) acc[i][j] = 0.0f;

    for (int kt = 0; kt < IN_F; kt += 32) {
        __syncthreads();
        for (int i = tid; i < 64 * 8; i += 256) {
            int r = i >> 3, c4 = i & 7;
            int gr = m0 + r;
            float4 v = make_float4(0.f, 0.f, 0.f, 0.f);
            if (gr < N_NODES)
                v = *(const float4*)&X[(size_t)gr * IN_F + kt + c4 * 4];
            *(float4*)&sX[r * 36 + c4 * 4] = v;
        }
        __syncthreads();

#pragma unroll
        for (int kk = 0; kk < 32; kk++) {
            float4 w4 = ((const float4*)(sW + (kt + kk) * HID_F))[tx];
            float a0 = sX[(ty * 4 + 0) * 36 + kk];
            float a1 = sX[(ty * 4 + 1) * 36 + kk];
            float a2 = sX[(ty * 4 + 2) * 36 + kk];
            float a3 = sX[(ty * 4 + 3) * 36 + kk];
            acc[0][0] = fmaf(a0, w4.x, acc[0][0]);
            acc[0][1] = fmaf(a0, w4.y, acc[0][1]);
            acc[0][2] = fmaf(a0, w4.z, acc[0][2]);
            acc[0][3] = fmaf(a0, w4.w, acc[0][3]);
            acc[1][0] = fmaf(a1, w4.x, acc[1][0]);
            acc[1][1] = fmaf(a1, w4.y, acc[1][1]);
            acc[1][2] = fmaf(a1, w4.z, acc[1][2]);
            acc[1][3] = fmaf(a1, w4.w, acc[1][3]);
            acc[2][0] = fmaf(a2, w4.x, acc[2][0]);
            acc[2][1] = fmaf(a2, w4.y, acc[2][1]);
            acc[2][2] = fmaf(a2, w4.z, acc[2][2]);
            acc[2][3] = fmaf(a2, w4.w, acc[2][3]);
            acc[3][0] = fmaf(a3, w4.x, acc[3][0]);
            acc[3][1] = fmaf(a3, w4.y, acc[3][1]);
            acc[3][2] = fmaf(a3, w4.z, acc[3][2]);
            acc[3][3] = fmaf(a3, w4.w, acc[3][3]);
        }
    }

#pragma unroll
    for (int i = 0; i < 4; i++) {
        int gr = m0 + ty * 4 + i;
        if (gr < N_NODES) {
            float4 o = make_float4(acc[i][0], acc[i][1], acc[i][2], acc[i][3]);
            *(float4*)&gv56_xw1[(size_t)gr * HID_F + tx * 4] = o;
        }
    }
}

// ---------------- scale+compress: xwsh = half(dinv ⊙ xw1) --------------------
__global__ __launch_bounds__(256) void k_scale() {
    int i = blockIdx.x * 256 + threadIdx.x;   // float4 group index; grid 6250
    int row = i >> 4;
    float dv = gv56_dinv[row];
    float4 v = ((const float4*)gv56_xw1)[i];
    __half2 h0 = __floats2half2_rn(v.x * dv, v.y * dv);
    __half2 h1 = __floats2half2_rn(v.z * dv, v.w * dv);
    uint2 packed;
    packed.x = *(const unsigned*)&h0;
    packed.y = *(const unsigned*)&h1;
    *(uint2*)&gv56_xwsh[i * 2] = packed;
}

// ---------------- prop1: paired-row gather (16 lanes per fp16 row) -----------
// lanes 0-15 gather edge g=0, lanes 16-31 edge g=1; combine via shfl.
__global__ __launch_bounds__(256) void k_prop1(const float* __restrict__ b1) {
    const int warp = threadIdx.x >> 5;
    const int lane = threadIdx.x & 31;
    const int g    = lane >> 4;               // 0 or 1
    const int l16  = lane & 15;               // uint2 index in row (4 feats)
    const int v = blockIdx.x * 8 + warp;      // grid 12500 exact

    const uint2* __restrict__ xwp = (const uint2*)gv56_xwsh;  // 16 uint2 per row

    float4 acc = make_float4(0.f, 0.f, 0.f, 0.f);

    int p = gv56_rowptr[v];
    const int e = gv56_rowptr[v + 1];         // (e - p) % 4 == 0
    for (; p + 8 <= e; p += 8) {
        int4 c0 = *(const int4*)&gv56_col[p];
        int4 c1 = *(const int4*)&gv56_col[p + 4];
        int u0 = g ? c0.y : c0.x;
        int u1 = g ? c0.w : c0.z;
        int u2 = g ? c1.y : c1.x;
        int u3 = g ? c1.w : c1.z;
        uint2 w0 = xwp[(size_t)u0 * 16 + l16];
        uint2 w1 = xwp[(size_t)u1 * 16 + l16];
        uint2 w2 = xwp[(size_t)u2 * 16 + l16];
        uint2 w3 = xwp[(size_t)u3 * 16 + l16];
#pragma unroll
        for (int k = 0; k < 4; k++) {
            uint2 w = (k == 0) ? w0 : (k == 1) ? w1 : (k == 2) ? w2 : w3;
            float2 fa = __half22float2(*(const __half2*)&w.x);
            float2 fb = __half22float2(*(const __half2*)&w.y);
            acc.x += fa.x; acc.y += fa.y; acc.z += fb.x; acc.w += fb.y;
        }
    }
    if (p < e) {                              // one remaining 4-group
        int4 c0 = *(const int4*)&gv56_col[p];
        int u0 = g ? c0.y : c0.x;
        int u1 = g ? c0.w : c0.z;
        uint2 w0 = xwp[(size_t)u0 * 16 + l16];
        uint2 w1 = xwp[(size_t)u1 * 16 + l16];
        float2 fa = __half22float2(*(const __half2*)&w0.x);
        float2 fb = __half22float2(*(const __half2*)&w0.y);
        acc.x += fa.x; acc.y += fa.y; acc.z += fb.x; acc.w += fb.y;
        fa = __half22float2(*(const __half2*)&w1.x);
        fb = __half22float2(*(const __half2*)&w1.y);
        acc.x += fa.x; acc.y += fa.y; acc.z += fb.x; acc.w += fb.y;
    }

    // combine the two edge-groups: lanes 0-15 += lanes 16-31
    acc.x += __shfl_down_sync(0xffffffffu, acc.x, 16);
    acc.y += __shfl_down_sync(0xffffffffu, acc.y, 16);
    acc.z += __shfl_down_sync(0xffffffffu, acc.z, 16);
    acc.w += __shfl_down_sync(0xffffffffu, acc.w, 16);

    if (g == 0) {
        float dv = gv56_dinv[v];
        float4 self = ((const float4*)gv56_xw1)[(size_t)v * 16 + l16];
        float4 bb = ((const float4*)b1)[l16];
        // total = dv*xw1[v] + gathered (both are "xws" scale)
        float tx_ = fmaf(dv, self.x, acc.x);
        float ty_ = fmaf(dv, self.y, acc.y);
        float tz_ = fmaf(dv, self.z, acc.z);
        float tw_ = fmaf(dv, self.w, acc.w);
        float4 o;
        o.x = fmaxf(fmaf(tx_, dv, bb.x), 0.0f);
        o.y = fmaxf(fmaf(ty_, dv, bb.y), 0.0f);
        o.z = fmaxf(fmaf(tz_, dv, bb.z), 0.0f);
        o.w = fmaxf(fmaf(tw_, dv, bb.w), 0.0f);
        ((float4*)gv56_h1)[(size_t)v * 16 + l16] = o;
    }
}

// ---------------- GEMM2: hw2s = dinv ⊙ (h1 @ W2) -----------------------------
__global__ __launch_bounds__(256) void k_gemm2(const float* __restrict__ W2) {
    __shared__ __align__(16) float sW[HID_F * CLS_F];  // 8 KB
    __shared__ __align__(16) float sX[64 * 68];        // 17.4 KB

    const int tid = threadIdx.x;
    const int m0 = blockIdx.x * 64;
    const int tx = tid & 7;
    const int ty = tid >> 3;

    for (int i = tid; i < HID_F * CLS_F / 4; i += 256)
        ((float4*)sW)[i] = ((const float4*)W2)[i];

    for (int i = tid; i < 64 * 16; i += 256) {
        int r = i >> 4, c4 = i & 15;
        int gr = m0 + r;
        float4 vv = make_float4(0.f, 0.f, 0.f, 0.f);
        if (gr < N_NODES)
            vv = *(const float4*)&gv56_h1[(size_t)gr * HID_F + c4 * 4];
        *(float4*)&sX[r * 68 + c4 * 4] = vv;
    }
    __syncthreads();

    float acc[2][4] = {{0.f, 0.f, 0.f, 0.f}, {0.f, 0.f, 0.f, 0.f}};
#pragma unroll
    for (int k = 0; k < HID_F; k++) {
        float4 w4 = *(const float4*)&sW[k * CLS_F + tx * 4];
        float a0 = sX[(ty * 2 + 0) * 68 + k];
        float a1 = sX[(ty * 2 + 1) * 68 + k];
        acc[0][0] = fmaf(a0, w4.x, acc[0][0]);
        acc[0][1] = fmaf(a0, w4.y, acc[0][1]);
        acc[0][2] = fmaf(a0, w4.z, acc[0][2]);
        acc[0][3] = fmaf(a0, w4.w, acc[0][3]);
        acc[1][0] = fmaf(a1, w4.x, acc[1][0]);
        acc[1][1] = fmaf(a1, w4.y, acc[1][1]);
        acc[1][2] = fmaf(a1, w4.z, acc[1][2]);
        acc[1][3] = fmaf(a1, w4.w, acc[1][3]);
    }

#pragma unroll
    for (int i = 0; i < 2; i++) {
        int gr = m0 + ty * 2 + i;
        if (gr < N_NODES) {
            float dv = gv56_dinv[gr];
            float4 o = make_float4(acc[i][0] * dv, acc[i][1] * dv,
                                   acc[i][2] * dv, acc[i][3] * dv);
            *(float4*)&gv56_hw2s[(size_t)gr * CLS_F + tx * 4] = o;
        }
    }
}

// ---------------- prop2: paired-row gather (16 lanes per fp32 row) -----------
__global__ __launch_bounds__(256) void k_prop2(const float* __restrict__ b2,
                                               float* __restrict__ out) {
    const int warp = threadIdx.x >> 5;
    const int lane = threadIdx.x & 31;
    const int g    = lane >> 4;
    const int l16  = lane & 15;               // float2 index in row (2 feats)
    const int v = blockIdx.x * 8 + warp;      // grid 12500 exact

    const float2* __restrict__ hwp = (const float2*)gv56_hw2s;  // 16 float2 per row

    float2 acc = make_float2(0.f, 0.f);

    int p = gv56_rowptr[v];
    const int e = gv56_rowptr[v + 1];
    for (; p + 8 <= e; p += 8) {
        int4 c0 = *(const int4*)&gv56_col[p];
        int4 c1 = *(const int4*)&gv56_col[p + 4];
        int u0 = g ? c0.y : c0.x;
        int u1 = g ? c0.w : c0.z;
        int u2 = g ? c1.y : c1.x;
        int u3 = g ? c1.w : c1.z;
        float2 f0 = hwp[(size_t)u0 * 16 + l16];
        float2 f1 = hwp[(size_t)u1 * 16 + l16];
        float2 f2 = hwp[(size_t)u2 * 16 + l16];
        float2 f3 = hwp[(size_t)u3 * 16 + l16];
        acc.x += f0.x + f1.x + f2.x + f3.x;
        acc.y += f0.y + f1.y + f2.y + f3.y;
    }
    if (p < e) {
        int4 c0 = *(const int4*)&gv56_col[p];
        int u0 = g ? c0.y : c0.x;
        int u1 = g ? c0.w : c0.z;
        float2 f0 = hwp[(size_t)u0 * 16 + l16];
        float2 f1 = hwp[(size_t)u1 * 16 + l16];
        acc.x += f0.x + f1.x;
        acc.y += f0.y + f1.y;
    }

    acc.x += __shfl_down_sync(0xffffffffu, acc.x, 16);
    acc.y += __shfl_down_sync(0xffffffffu, acc.y, 16);

    if (g == 0) {
        float dv = gv56_dinv[v];
        float2 self = hwp[(size_t)v * 16 + l16];
        float2 bb = ((const float2*)b2)[l16];
        float2 o;
        o.x = fmaf(acc.x + self.x, dv, bb.x);
        o.y = fmaf(acc.y + self.y, dv, bb.y);
        ((float2*)out)[(size_t)v * 16 + l16] = o;
    }
}

// ---------------- launch ------------------------------------------------------
extern "C" void kernel_launch(void* const* d_in, const int* in_sizes, int n_in,
                              void* d_out, int out_size) {
    static cudaStream_t s2 = nullptr;
    static cudaEvent_t evFork = nullptr, evScan = nullptr, evScale = nullptr;
    if (s2 == nullptr) {
        int loPri = 0, hiPri = 0;
        cudaDeviceGetStreamPriorityRange(&loPri, &hiPri);
        cudaStreamCreateWithPriority(&s2, cudaStreamNonBlocking, hiPri);
        cudaEventCreateWithFlags(&evFork, cudaEventDisableTiming);
        cudaEventCreateWithFlags(&evScan, cudaEventDisableTiming);
        cudaEventCreateWithFlags(&evScale, cudaEventDisableTiming);
    }

    const float* x  = nullptr;
    const void*  ei = nullptr;
    const float* W1 = nullptr;
    const float* b1 = nullptr;
    const float* W2 = nullptr;
    const float* b2 = nullptr;

    for (int i = 0; i < n_in; i++) {
        switch (in_sizes[i]) {
            case N_NODES * IN_F:  x  = (const float*)d_in[i]; break;
            case 2 * N_EDGES:     ei = d_in[i];               break;
            case N_EDGES:         /* edge_attr unused */       break;
            case IN_F * HID_F:    W1 = (const float*)d_in[i]; break;
            case HID_F:           b1 = (const float*)d_in[i]; break;
            case HID_F * CLS_F:   W2 = (const float*)d_in[i]; break;
            case CLS_F:           b2 = (const float*)d_in[i]; break;
            default: break;
        }
    }
    if (!x)  x  = (const float*)d_in[0];
    if (!ei) ei = d_in[1];
    if (!W1 && n_in > 3) W1 = (const float*)d_in[3];
    if (!b1 && n_in > 4) b1 = (const float*)d_in[4];
    if (!W2 && n_in > 5) W2 = (const float*)d_in[5];
    if (!b2 && n_in > 6) b2 = (const float*)d_in[6];

    float* out = (float*)d_out;

    // fork: gemm1 (high-priority s2) ∥ CSR build (main)
    cudaEventRecord(evFork, 0);
    cudaStreamWaitEvent(s2, evFork, 0);
    k_gemm1<<<(N_NODES + 63) / 64, 256, 0, s2>>>(x, W1);

    k_count<<<(N_EDGES / 4 + 255) / 256, 256>>>(ei);
    k_scan <<<NBLK, 256>>>(0);
    cudaEventRecord(evScan, 0);
    cudaStreamWaitEvent(s2, evScan, 0);
    k_scale<<<N_NODES * HID_F / 4 / 256, 256, 0, s2>>>();
    cudaEventRecord(evScale, s2);

    k_fill <<<(N_EDGES / 4 + 255) / 256, 256>>>(ei);

    cudaStreamWaitEvent(0, evScale, 0);
    k_prop1<<<N_NODES / 8, 256>>>(b1);
    k_gemm2<<<(N_NODES + 63) / 64, 256>>>(W2);
    k_prop2<<<N_NODES / 8, 256>>>(b2, out);
}